// round 16
// baseline (speedup 1.0000x reference)
#include <cuda_runtime.h>
#include <math.h>
#include <stdint.h>

#define BATCH 2
#define CH 256
#define HH 56
#define WW 56
#define NP (HH*WW)        /* 3136 */
#define NPP 3200          /* padded token dim */
#define NH 8
#define DH 32
#define KCNT1 1568        /* N1 // 2 */
#define KCNT2 1045        /* N1 // 3 */
#define LN_EPS 1e-5f
#define SCALE 0.17677669529663687f  /* 1/sqrt(32) */

// ---------------- scratch (static device globals; no allocation) ------------
// Pad rows [NP, NPP) of g_q/g_k/g_v are NEVER written -> packed bf16 zero.
__device__ __align__(16) float    g_pool[BATCH*CH*NP];
__device__ __align__(16) float    g_yln [BATCH*NP*CH];
__device__ __align__(16) unsigned g_q   [BATCH*NH*NPP*DH];   // packed (hi<<16)|lo
__device__ __align__(16) unsigned g_k   [BATCH*NH*NPP*DH];   // packed
__device__ __align__(16) unsigned g_v   [BATCH*NH*NPP*DH];   // packed
__device__ __align__(16) float    g_ao  [BATCH*NPP*CH];

// ====== helpers ==============================================================
__device__ __forceinline__ void sc_bfsplit(float v, unsigned &hi16, unsigned &lo16) {
    unsigned u = __float_as_uint(v);
    unsigned t = u + 0x7FFFu + ((u >> 16) & 1u);
    hi16 = t >> 16;
    float r = v - __uint_as_float(hi16 << 16);
    unsigned ur = __float_as_uint(r);
    unsigned tr = ur + 0x7FFFu + ((ur >> 16) & 1u);
    lo16 = tr >> 16;
}
__device__ __forceinline__ unsigned pack_split(float v) {
    unsigned hi, lo;
    sc_bfsplit(v, hi, lo);
    return (hi << 16) | lo;
}
__device__ __forceinline__ void mma_bf16(float* d, const unsigned* a, const unsigned* b) {
    asm volatile(
        "mma.sync.aligned.m16n8k16.row.col.f32.bf16.bf16.f32 "
        "{%0,%1,%2,%3}, {%4,%5,%6,%7}, {%8,%9}, {%0,%1,%2,%3};"
        : "+f"(d[0]), "+f"(d[1]), "+f"(d[2]), "+f"(d[3])
        : "r"(a[0]), "r"(a[1]), "r"(a[2]), "r"(a[3]), "r"(b[0]), "r"(b[1]));
}
__device__ __forceinline__ unsigned xfrm(float v) {
    unsigned u = __float_as_uint(v);
    return u ^ ((u & 0x80000000u) ? 0xFFFFFFFFu : 0x80000000u);
}
// warp-synchronous 256-bin suffix select: returns residual r', sets selB
__device__ __forceinline__ int warp_sel(const unsigned* hw, int r, int lane,
                                        unsigned &selB) {
    int l8 = lane * 8;
    unsigned h[8], s[8];
    #pragma unroll
    for (int j = 0; j < 8; j++) h[j] = hw[l8 + j];
    s[7] = h[7];
    #pragma unroll
    for (int j = 6; j >= 0; j--) s[j] = h[j] + s[j+1];
    unsigned tot = s[0];
    unsigned v = tot;
    #pragma unroll
    for (int off = 1; off < 32; off <<= 1) {
        unsigned u = __shfl_down_sync(0xFFFFFFFFu, v, off);
        if (lane + off < 32) v += u;
    }
    unsigned higher = v - tot;
    int fB = -1, fr = 0;
    #pragma unroll
    for (int j = 0; j < 8; j++) {
        unsigned Sj = s[j] + higher;
        unsigned ab = Sj - h[j];
        if (Sj >= (unsigned)r && ab < (unsigned)r) { fB = l8 + j; fr = r - (int)ab; }
    }
    unsigned bal = __ballot_sync(0xFFFFFFFFu, fB >= 0);
    int src = __ffs(bal) - 1;
    selB = (unsigned)__shfl_sync(0xFFFFFFFFu, fB, src);
    return __shfl_sync(0xFFFFFFFFu, fr, src);
}

// ---------------- 1) multiscale avg pool -------------------------------------
__global__ __launch_bounds__(256) void pool_kernel(const float* __restrict__ y) {
    __shared__ float plane[NP];
    int bc = blockIdx.x;
    const float* src = y + (size_t)bc * NP;
    for (int i = threadIdx.x; i < NP; i += 256) plane[i] = src[i];
    __syncthreads();
    for (int i = threadIdx.x; i < NP; i += 256) {
        int r = i / WW, c = i % WW;
        float s3 = 0.f, s5 = 0.f, s7 = 0.f;
        #pragma unroll
        for (int dr = -3; dr <= 3; dr++) {
            int rr = r + dr; if (rr < 0 || rr >= HH) continue;
            #pragma unroll
            for (int dc = -3; dc <= 3; dc++) {
                int cc = c + dc; if (cc < 0 || cc >= WW) continue;
                float v = plane[rr*WW + cc];
                s7 += v;
                if (dr >= -2 && dr <= 2 && dc >= -2 && dc <= 2) s5 += v;
                if (dr >= -1 && dr <= 1 && dc >= -1 && dc <= 1) s3 += v;
            }
        }
        g_pool[(size_t)bc*NP + i] = s3*(1.f/9.f) + s5*(1.f/25.f) + s7*(1.f/49.f);
    }
}

// ---------------- 2) LayerNorm ----------------------------------------------
__global__ __launch_bounds__(256) void ln_kernel(const float* __restrict__ ln_w,
                                                 const float* __restrict__ ln_b) {
    __shared__ float red[256];
    int bn = blockIdx.x;
    int b = bn / NP, n = bn % NP;
    int c = threadIdx.x;
    float v = g_pool[((size_t)b*CH + c)*NP + n];
    red[c] = v; __syncthreads();
    for (int off = 128; off > 0; off >>= 1) {
        if (c < off) red[c] += red[c + off];
        __syncthreads();
    }
    float mean = red[0] * (1.f/CH);
    __syncthreads();
    float dv = v - mean;
    red[c] = dv * dv; __syncthreads();
    for (int off = 128; off > 0; off >>= 1) {
        if (c < off) red[c] += red[c + off];
        __syncthreads();
    }
    float var = red[0] * (1.f/CH);
    g_yln[(size_t)bn*CH + c] = dv * rsqrtf(var + LN_EPS) * ln_w[c] + ln_b[c];
}

// ---------------- 3) KV GEMM -> packed split-bf16 k, v ----------------------
__global__ __launch_bounds__(256) void kv_gemm(const float* __restrict__ kv_w,
                                               const float* __restrict__ kv_b) {
    __shared__ float As[16][65];
    __shared__ float Bs[16][65];
    int b  = blockIdx.z;
    int m0 = blockIdx.x * 64;
    int o0 = blockIdx.y * 64;
    int tid = threadIdx.x, tx = tid & 15, ty = tid >> 4;
    float acc[4][4] = {};
    for (int k0 = 0; k0 < CH; k0 += 16) {
        #pragma unroll
        for (int l = 0; l < 4; l++) {
            int idx = tid + l*256; int k = idx & 15, m = idx >> 4;
            As[k][m] = g_yln[((size_t)b*NP + m0 + m)*CH + k0 + k];
        }
        #pragma unroll
        for (int l = 0; l < 4; l++) {
            int idx = tid + l*256; int k = idx & 15, o = idx >> 4;
            Bs[k][o] = kv_w[(size_t)(o0 + o)*CH + k0 + k];
        }
        __syncthreads();
        #pragma unroll
        for (int kk = 0; kk < 16; kk++) {
            float a[4], bb[4];
            #pragma unroll
            for (int i = 0; i < 4; i++) a[i]  = As[kk][ty*4 + i];
            #pragma unroll
            for (int j = 0; j < 4; j++) bb[j] = Bs[kk][tx*4 + j];
            #pragma unroll
            for (int i = 0; i < 4; i++)
                #pragma unroll
                for (int j = 0; j < 4; j++) acc[i][j] += a[i]*bb[j];
        }
        __syncthreads();
    }
    #pragma unroll
    for (int i = 0; i < 4; i++) {
        int n = m0 + ty*4 + i;
        #pragma unroll
        for (int j = 0; j < 4; j++) {
            int o = o0 + tx*4 + j;
            float r = acc[i][j] + kv_b[o];
            unsigned p = pack_split(r);
            if (o < 256) {
                int hh = o >> 5, dd = o & 31;
                g_k[(((size_t)b*NH + hh)*NPP + n)*DH + dd] = p;
            } else {
                int oo = o - 256; int hh = oo >> 5, dd = oo & 31;
                g_v[(((size_t)b*NH + hh)*NPP + n)*DH + dd] = p;
            }
        }
    }
}

// ---------------- 4) Q GEMM -> packed split-bf16 q ---------------------------
__global__ __launch_bounds__(256) void q_gemm(const float* __restrict__ x,
                                              const float* __restrict__ q_w,
                                              const float* __restrict__ q_b) {
    __shared__ float As[16][65];
    __shared__ float Bs[16][65];
    int b  = blockIdx.z;
    int m0 = blockIdx.x * 64;
    int o0 = blockIdx.y * 64;
    const float* xb = x + (size_t)b*CH*NP;
    int tid = threadIdx.x, tx = tid & 15, ty = tid >> 4;
    float acc[4][4] = {};
    for (int k0 = 0; k0 < CH; k0 += 16) {
        #pragma unroll
        for (int l = 0; l < 4; l++) {
            int idx = tid + l*256; int m = idx & 63, k = idx >> 6;
            As[k][m] = xb[(size_t)(k0 + k)*NP + m0 + m];
        }
        #pragma unroll
        for (int l = 0; l < 4; l++) {
            int idx = tid + l*256; int k = idx & 15, o = idx >> 4;
            Bs[k][o] = q_w[(size_t)(o0 + o)*CH + k0 + k];
        }
        __syncthreads();
        #pragma unroll
        for (int kk = 0; kk < 16; kk++) {
            float a[4], bb[4];
            #pragma unroll
            for (int i = 0; i < 4; i++) a[i]  = As[kk][ty*4 + i];
            #pragma unroll
            for (int j = 0; j < 4; j++) bb[j] = Bs[kk][tx*4 + j];
            #pragma unroll
            for (int i = 0; i < 4; i++)
                #pragma unroll
                for (int j = 0; j < 4; j++) acc[i][j] += a[i]*bb[j];
        }
        __syncthreads();
    }
    #pragma unroll
    for (int i = 0; i < 4; i++) {
        int n = m0 + ty*4 + i;
        #pragma unroll
        for (int j = 0; j < 4; j++) {
            int o = o0 + tx*4 + j;
            int hh = o >> 5, dd = o & 31;
            g_q[(((size_t)b*NH + hh)*NPP + n)*DH + dd] = pack_split(acc[i][j] + q_b[o]);
        }
    }
}

// ====== 5) FUSED attention: score + exact topk softmax + W@V ================
#define SST 3204                       /* S row stride in u32 */
#define FS_K (16*SST)                  /* 51264 */
#define FS_Q (FS_K + 64*52)            /* 54592 */
#define FS_H (FS_Q + 16*33)            /* 55120 */
#define FS_U32 (FS_H + 8*256)          /* 57168 u32 */
#define FS_BYTES (FS_U32*4)            /* 228672 B */

__global__ __launch_bounds__(256, 1) void attn_fused(const float* __restrict__ p1p,
                                                     const float* __restrict__ p2p) {
    extern __shared__ unsigned sm[];
    unsigned* S  = sm;                 // [16][SST] scores -> packed weights
    unsigned* KB = sm + FS_K;          // [64][52] k staging
    unsigned* QB = sm + FS_Q;          // [16][33] packed q
    unsigned* HB = sm + FS_H;          // [8][256] per-warp hist; later reduce buf
    float* Sf = (float*)S;

    int tid = threadIdx.x;
    int wid = tid >> 5, lane = tid & 31;
    int g = lane >> 2, tig = lane & 3;
    int n0 = blockIdx.x * 16;
    int bh = blockIdx.y;
    int b = bh >> 3, hh = bh & 7;

    // ---- load packed q rows -------------------------------------------------
    for (int e = tid; e < 512; e += 256) {
        int r = e >> 5, d = e & 31;
        QB[r*33 + d] = g_q[((size_t)bh*NPP + n0 + r)*DH + d];
    }
    __syncthreads();

    // ---- q fragments (held in regs for all of phase A) ----------------------
    unsigned aH[4], aH2[4], aL[4], aL2[4];
    {
        #pragma unroll
        for (int jj = 0; jj < 4; jj++) {
            int j = tig + jj*4;
            unsigned p0 = QB[g*33 + 2*j],     p1 = QB[g*33 + 2*j + 1];
            unsigned q0 = QB[(g+8)*33 + 2*j], q1 = QB[(g+8)*33 + 2*j + 1];
            unsigned h0 = (p0 >> 16) | (p1 & 0xFFFF0000u);
            unsigned l0 = (p0 & 0xFFFFu) | (p1 << 16);
            unsigned h1 = (q0 >> 16) | (q1 & 0xFFFF0000u);
            unsigned l1 = (q0 & 0xFFFFu) | (q1 << 16);
            if (jj == 0) { aH[0]=h0; aH[1]=h1; aL[0]=l0; aL[1]=l1; }
            if (jj == 1) { aH[2]=h0; aH[3]=h1; aL[2]=l0; aL[3]=l1; }
            if (jj == 2) { aH2[0]=h0; aH2[1]=h1; aL2[0]=l0; aL2[1]=l1; }
            if (jj == 3) { aH2[2]=h0; aH2[3]=h1; aL2[2]=l0; aL2[3]=l1; }
        }
    }

    // ================= Phase A: scores into smem ============================
    const unsigned* kb_g = g_k + (size_t)bh*NPP*DH;
    for (int c0 = 0; c0 < NPP; c0 += 64) {
        // build KB = [k_hi | k_lo | k_hi] for k rows c0..c0+63
        #pragma unroll
        for (int l = 0; l < 4; l++) {
            int e = tid + l*256;
            int n = e >> 4, j = e & 15;
            uint2 p = *(const uint2*)(kb_g + (size_t)(c0 + n)*DH + 2*j);
            unsigned kh = (p.x >> 16) | (p.y & 0xFFFF0000u);
            unsigned kl = (p.x & 0xFFFFu) | (p.y << 16);
            KB[n*52 + j]      = kh;
            KB[n*52 + 16 + j] = kl;
            KB[n*52 + 32 + j] = kh;
        }
        __syncthreads();
        float acc[4] = {0.f, 0.f, 0.f, 0.f};
        const unsigned* kr = KB + (wid*8 + g)*52;
        unsigned bf[2];
        bf[0] = kr[tig];      bf[1] = kr[tig + 4];  mma_bf16(acc, aH,  bf);
        bf[0] = kr[8 + tig];  bf[1] = kr[12 + tig]; mma_bf16(acc, aH2, bf);
        bf[0] = kr[16 + tig]; bf[1] = kr[20 + tig]; mma_bf16(acc, aH,  bf);
        bf[0] = kr[24 + tig]; bf[1] = kr[28 + tig]; mma_bf16(acc, aH2, bf);
        bf[0] = kr[32 + tig]; bf[1] = kr[36 + tig]; mma_bf16(acc, aL,  bf);
        bf[0] = kr[40 + tig]; bf[1] = kr[44 + tig]; mma_bf16(acc, aL2, bf);
        int col = c0 + wid*8 + tig*2;
        *(float2*)&Sf[g*SST + col]     = make_float2(acc[0]*SCALE, acc[1]*SCALE);
        *(float2*)&Sf[(g+8)*SST + col] = make_float2(acc[2]*SCALE, acc[3]*SCALE);
        __syncthreads();
    }

    // ================= Phase B: warp-per-row exact topk softmax =============
    float p1 = p1p[0], p2 = p2p[0];
    unsigned* hw = HB + wid*256;
    for (int rr = 0; rr < 2; rr++) {
        int row = wid + rr*8;
        float* rowf = Sf + row*SST;
        // pass 1: max + level-0 histogram (match-aggregated atomics)
        for (int bI = lane; bI < 256; bI += 32) hw[bI] = 0u;
        __syncwarp();
        unsigned lmax = 0u;
        for (int i = lane; i < NP; i += 32) {
            unsigned u = xfrm(rowf[i]);
            lmax = max(lmax, u);
            unsigned byte = u >> 24;
            unsigned mm = __match_any_sync(0xFFFFFFFFu, byte);
            if (lane == __ffs(mm) - 1) atomicAdd(&hw[byte], (unsigned)__popc(mm));
        }
        #pragma unroll
        for (int off = 16; off > 0; off >>= 1)
            lmax = max(lmax, __shfl_xor_sync(0xFFFFFFFFu, lmax, off));
        float rowmax = __uint_as_float(lmax ^ ((lmax & 0x80000000u) ? 0x80000000u
                                                                   : 0xFFFFFFFFu));
        __syncwarp();
        unsigned B1, B2;
        int r1 = warp_sel(hw, KCNT1, lane, B1);
        int r2 = warp_sel(hw, KCNT2, lane, B2);
        // levels 1..3 for each selection
        unsigned thr[2];
        unsigned selB0[2] = {B1, B2};
        int selR0[2] = {r1, r2};
        for (int s = 0; s < 2; s++) {
            unsigned prefix = selB0[s] << 24;
            unsigned mask   = 0xFF000000u;
            int r = selR0[s];
            for (int shift = 16; shift >= 0; shift -= 8) {
                for (int bI = lane; bI < 256; bI += 32) hw[bI] = 0u;
                __syncwarp();
                for (int i = lane; i < NP; i += 32) {
                    unsigned u = xfrm(rowf[i]);
                    bool pr = (u & mask) == prefix;
                    unsigned key = pr ? ((u >> shift) & 255u) : (0x100u + lane);
                    unsigned mm = __match_any_sync(0xFFFFFFFFu, key);
                    if (pr && lane == __ffs(mm) - 1)
                        atomicAdd(&hw[key], (unsigned)__popc(mm));
                }
                __syncwarp();
                unsigned sb;
                r = warp_sel(hw, r, lane, sb);
                prefix |= sb << shift;
                mask   |= 0xFFu << shift;
            }
            thr[s] = prefix;
        }
        // Z pass: exp only for selected; cache +/-e in place (sign = thr2 flag)
        float z1 = 0.f, z2 = 0.f;
        for (int i = lane; i < NP; i += 32) {
            float v = rowf[i];
            unsigned u = xfrm(v);
            float st = 0.f;
            if (u >= thr[0]) {
                float e = __expf(v - rowmax);
                z1 += e;
                if (u >= thr[1]) { z2 += e; st = -e; }
                else st = e;
            }
            rowf[i] = st;
        }
        #pragma unroll
        for (int off = 16; off > 0; off >>= 1) {
            z1 += __shfl_xor_sync(0xFFFFFFFFu, z1, off);
            z2 += __shfl_xor_sync(0xFFFFFFFFu, z2, off);
        }
        float c1 = p1 / z1, c2 = p2 / z2;
        // weight pass: packed split-bf16 in place
        unsigned* rowu = (unsigned*)rowf;
        for (int i = lane; i < NP; i += 32) {
            float t = rowf[i];
            float wgt = (t == 0.f) ? 0.f : (t < 0.f ? (c1 + c2)*(-t) : c1*t);
            rowu[i] = pack_split(wgt);
        }
        // cols [NP, NPP) still hold score 0.0f == packed zero -> contribute 0
    }
    __syncthreads();

    // ================= Phase C: out = W @ V =================================
    int nt = wid & 3, kh2 = wid >> 2;
    float acc[4] = {0.f, 0.f, 0.f, 0.f};
    int dd = nt*8 + g;
    const unsigned* vb = g_v + (size_t)bh*NPP*DH + dd;
    for (int c = kh2*50; c < kh2*50 + 50; c++) {
        int k0 = c*32;
        unsigned wH[4], wH2[4], wL[4], wL2[4];
        #pragma unroll
        for (int jj = 0; jj < 4; jj++) {
            int j = tig + jj*4;
            uint2 p = *(const uint2*)&S[g*SST + k0 + 2*j];
            uint2 q = *(const uint2*)&S[(g+8)*SST + k0 + 2*j];
            unsigned h0 = (p.x >> 16) | (p.y & 0xFFFF0000u);
            unsigned l0 = (p.x & 0xFFFFu) | (p.y << 16);
            unsigned h1 = (q.x >> 16) | (q.y & 0xFFFF0000u);
            unsigned l1 = (q.x & 0xFFFFu) | (q.y << 16);
            if (jj == 0) { wH[0]=h0; wH[1]=h1; wL[0]=l0; wL[1]=l1; }
            if (jj == 1) { wH[2]=h0; wH[3]=h1; wL[2]=l0; wL[3]=l1; }
            if (jj == 2) { wH2[0]=h0; wH2[1]=h1; wL2[0]=l0; wL2[1]=l1; }
            if (jj == 3) { wH2[2]=h0; wH2[3]=h1; wL2[2]=l0; wL2[3]=l1; }
        }
        unsigned bH[4], bL[4];
        #pragma unroll
        for (int jj = 0; jj < 4; jj++) {
            int j = tig + jj*4;
            unsigned p0 = vb[(size_t)(k0 + 2*j)*DH];
            unsigned p1 = vb[(size_t)(k0 + 2*j + 1)*DH];
            bH[jj] = (p0 >> 16) | (p1 & 0xFFFF0000u);
            bL[jj] = (p0 & 0xFFFFu) | (p1 << 16);
        }
        unsigned bf[2];
        bf[0] = bH[0]; bf[1] = bH[1]; mma_bf16(acc, wH,  bf);   // wh*vh
        bf[0] = bH[2]; bf[1] = bH[3]; mma_bf16(acc, wH2, bf);
        bf[0] = bL[0]; bf[1] = bL[1]; mma_bf16(acc, wH,  bf);   // wh*vl
        bf[0] = bL[2]; bf[1] = bL[3]; mma_bf16(acc, wH2, bf);
        bf[0] = bH[0]; bf[1] = bH[1]; mma_bf16(acc, wL,  bf);   // wl*vh
        bf[0] = bH[2]; bf[1] = bH[3]; mma_bf16(acc, wL2, bf);
    }
    __syncthreads();   // HB free for reduction
    float* rb = (float*)HB;
    if (kh2 == 1) {
        float* p = rb + ((wid - 4)*32 + lane)*4;
        p[0] = acc[0]; p[1] = acc[1]; p[2] = acc[2]; p[3] = acc[3];
    }
    __syncthreads();
    if (kh2 == 0) {
        float* p = rb + (wid*32 + lane)*4;
        acc[0] += p[0]; acc[1] += p[1]; acc[2] += p[2]; acc[3] += p[3];
        int colg = hh*DH + nt*8 + tig*2;
        float* o0p = &g_ao[((size_t)b*NPP + n0 + g)*CH + colg];
        float* o1p = &g_ao[((size_t)b*NPP + n0 + g + 8)*CH + colg];
        o0p[0] = acc[0]; o0p[1] = acc[1];
        o1p[0] = acc[2]; o1p[1] = acc[3];
    }
}

// ---------------- 8) projection + transposed store to [B,C,H,W] -------------
__global__ __launch_bounds__(256) void proj_gemm(const float* __restrict__ proj_w,
                                                 const float* __restrict__ proj_b,
                                                 float* __restrict__ out) {
    __shared__ float As[16][65];
    __shared__ float Bs[16][65];
    int b  = blockIdx.z;
    int m0 = blockIdx.x * 64;
    int o0 = blockIdx.y * 64;
    int tid = threadIdx.x, tx = tid & 15, ty = tid >> 4;
    float acc[4][4] = {};
    for (int k0 = 0; k0 < CH; k0 += 16) {
        #pragma unroll
        for (int l = 0; l < 4; l++) {
            int idx = tid + l*256; int k = idx & 15, m = idx >> 4;
            As[k][m] = g_ao[((size_t)b*NPP + m0 + m)*CH + k0 + k];
        }
        #pragma unroll
        for (int l = 0; l < 4; l++) {
            int idx = tid + l*256; int k = idx & 15, o = idx >> 4;
            Bs[k][o] = proj_w[(size_t)(o0 + o)*CH + k0 + k];
        }
        __syncthreads();
        #pragma unroll
        for (int kk = 0; kk < 16; kk++) {
            float a[4], bb[4];
            #pragma unroll
            for (int i = 0; i < 4; i++) a[i]  = As[kk][ty*4 + i];
            #pragma unroll
            for (int j = 0; j < 4; j++) bb[j] = Bs[kk][tx*4 + j];
            #pragma unroll
            for (int i = 0; i < 4; i++)
                #pragma unroll
                for (int j = 0; j < 4; j++) acc[i][j] += a[i]*bb[j];
        }
        __syncthreads();
    }
    #pragma unroll
    for (int i = 0; i < 4; i++) {
        int n = m0 + ty*4 + i;
        #pragma unroll
        for (int j = 0; j < 4; j++) {
            int o = o0 + tx*4 + j;
            out[((size_t)b*CH + o)*NP + n] = acc[i][j] + proj_b[o];
        }
    }
}

// ---------------------------------------------------------------------------
extern "C" void kernel_launch(void* const* d_in, const int* in_sizes, int n_in,
                              void* d_out, int out_size) {
    (void)in_sizes; (void)n_in; (void)out_size;
    const float* x      = (const float*)d_in[0];
    const float* y      = (const float*)d_in[1];
    const float* q_w    = (const float*)d_in[2];
    const float* q_b    = (const float*)d_in[3];
    const float* kv_w   = (const float*)d_in[4];
    const float* kv_b   = (const float*)d_in[5];
    const float* proj_w = (const float*)d_in[6];
    const float* proj_b = (const float*)d_in[7];
    const float* ln_w   = (const float*)d_in[8];
    const float* ln_b   = (const float*)d_in[9];
    const float* p1     = (const float*)d_in[10];
    const float* p2     = (const float*)d_in[11];
    float* out = (float*)d_out;

    cudaFuncSetAttribute(attn_fused, cudaFuncAttributeMaxDynamicSharedMemorySize,
                         FS_BYTES);

    pool_kernel<<<BATCH*CH, 256>>>(y);
    ln_kernel  <<<BATCH*NP, 256>>>(ln_w, ln_b);
    kv_gemm    <<<dim3(NP/64, 512/64, BATCH), 256>>>(kv_w, kv_b);
    q_gemm     <<<dim3(NP/64, CH/64, BATCH), 256>>>(x, q_w, q_b);
    attn_fused <<<dim3(NP/16, BATCH*NH), 256, FS_BYTES>>>(p1, p2);
    proj_gemm  <<<dim3(NP/64, CH/64, BATCH), 256>>>(proj_w, proj_b, out);
}